// round 4
// baseline (speedup 1.0000x reference)
#include <cuda_runtime.h>
#include <cuda_bf16.h>
#include <float.h>
#include <stdint.h>

// Problem constants
#define BB 4
#define RR 128
#define CC 256
#define HH 64
#define WW 64
#define NREG 32
#define PS 3            // pool size (3x3)
#define IOU_THR 0.4f

// Scratch for clipped integer boxes (B*N*4). Device global per allocation rules.
__device__ int g_boxes[BB * NREG * 4];

// ---------------------------------------------------------------------------
// Kernel 1: per-batch NMS + index selection + ROI clipping.
// One block per batch, 128 threads (one per box).
// ---------------------------------------------------------------------------
__device__ __forceinline__ void fix_axis(int& mn, int& mx, int ps, int fs) {
    int pad = ps - (mx - mn);
    if (pad > 0) {
        bool fmin = mn < (pad / 2);            // pad>0 -> trunc == floor
        bool fmx  = (fs - mx) < ((1 + pad) / 2);
        if (!fmin && !fmx) { mn = mn - pad / 2; mx = mx + (1 + pad) / 2; }
        if (fmin) { mn = 0; mx = ps; }
        if (fmx)  { mn = fs - ps; mx = fs; }   // fmx overrides fmin (ref order)
    }
}

__global__ void nms_clip_kernel(const float* __restrict__ roi,
                                float* __restrict__ out_roic) {
    __shared__ float sx1[RR], sy1[RR], sx2[RR], sy2[RR], sar[RR];
    __shared__ uint32_t sup[RR][4];
    __shared__ int sel[NREG];

    const int b = blockIdx.x;
    const int t = threadIdx.x;

    // Load box t of batch b
    const float* rp = roi + ((size_t)b * RR + t) * 4;
    float x = rp[0], y = rp[1], w = rp[2], h = rp[3];
    float x2 = x + w, y2 = y + h, ar = w * h;
    sx1[t] = x;  sy1[t] = y;  sx2[t] = x2;  sy2[t] = y2;  sar[t] = ar;
    __syncthreads();

    // Row t of the suppression matrix: bit j set iff j > t and IoU(t, j) > thr.
    uint32_t row0 = 0, row1 = 0, row2 = 0, row3 = 0;
    for (int j = t + 1; j < RR; ++j) {
        float iw = fminf(x2, sx2[j]) - fmaxf(x, sx1[j]);
        iw = fmaxf(iw, 0.0f);
        float ih = fminf(y2, sy2[j]) - fmaxf(y, sy1[j]);
        ih = fmaxf(ih, 0.0f);
        float inter = iw * ih;
        float uni   = ar + sar[j] - inter;
        float iou   = __fdiv_rn(inter, uni);   // IEEE rn (matches jnp fp32 div)
        if (iou > IOU_THR) {
            uint32_t bit = 1u << (j & 31);
            if      ((j >> 5) == 0) row0 |= bit;
            else if ((j >> 5) == 1) row1 |= bit;
            else if ((j >> 5) == 2) row2 |= bit;
            else                    row3 |= bit;
        }
    }
    sup[t][0] = row0; sup[t][1] = row1; sup[t][2] = row2; sup[t][3] = row3;
    __syncthreads();

    // Serial greedy walk on a 128-bit keep mask (single thread, ~128 iters).
    if (t == 0) {
        uint32_t k0 = ~0u, k1 = ~0u, k2 = ~0u, k3 = ~0u;
        for (int p = 0; p < RR - 1; ++p) {
            uint32_t kw = (p < 32) ? k0 : (p < 64) ? k1 : (p < 96) ? k2 : k3;
            if ((kw >> (p & 31)) & 1u) {
                k0 &= ~sup[p][0]; k1 &= ~sup[p][1];
                k2 &= ~sup[p][2]; k3 &= ~sup[p][3];
            }
        }
        // Collect first NREG kept indices ascending; pad with R-1 (= min(R, R-1)).
        int cnt = 0;
        for (int p = 0; p < RR && cnt < NREG; ++p) {
            uint32_t kw = (p < 32) ? k0 : (p < 64) ? k1 : (p < 96) ? k2 : k3;
            if ((kw >> (p & 31)) & 1u) sel[cnt++] = p;
        }
        for (; cnt < NREG; ++cnt) sel[cnt] = RR - 1;
    }
    __syncthreads();

    // Threads 0..31: clip the selected ROI, write int scratch + float output tail.
    if (t < NREG) {
        int p = sel[t];
        float bx = sx1[p], by = sy1[p], bx2 = sx2[p], by2 = sy2[p];
        int xmn = (int)fmaxf(0.0f, bx);
        int ymn = (int)fmaxf(0.0f, by);
        int xmx = (int)fminf((float)WW, bx2);
        int ymx = (int)fminf((float)HH, by2);
        fix_axis(xmn, xmx, PS, WW);
        fix_axis(ymn, ymx, PS, HH);

        int o = (b * NREG + t) * 4;
        g_boxes[o + 0] = xmn;
        g_boxes[o + 1] = ymn;
        g_boxes[o + 2] = xmx - xmn;
        g_boxes[o + 3] = ymx - ymn;
        out_roic[o + 0] = (float)xmn;
        out_roic[o + 1] = (float)ymn;
        out_roic[o + 2] = (float)(xmx - xmn);
        out_roic[o + 3] = (float)(ymx - ymn);
    }
}

// ---------------------------------------------------------------------------
// Kernel 2: max-pool each (box, cell). Grid = B*N*9 blocks, 64 threads.
// Thread t owns channels [4t, 4t+4) as one float4; fully coalesced 1024B rows.
// ---------------------------------------------------------------------------
__global__ void __launch_bounds__(64) pool_kernel(const float* __restrict__ feat,
                                                  float* __restrict__ out) {
    const int bid  = blockIdx.x;        // 0 .. B*N*9-1
    const int box  = bid / 9;           // 0 .. B*N-1
    const int cell = bid - box * 9;
    const int ci   = cell / 3;          // row cell
    const int cj   = cell - ci * 3;     // col cell
    const int b    = box >> 5;          // box / NREG

    const int x = g_boxes[box * 4 + 0];
    const int y = g_boxes[box * 4 + 1];
    const int w = g_boxes[box * 4 + 2];
    const int h = g_boxes[box * 4 + 3];

    const int d = h / PS;               // >= 1 (h >= 3 guaranteed by clip)
    const int e = w / PS;
    const int r0 = y + ci * d;
    const int r1 = (ci < 2) ? (r0 + d) : (y + h);   // last cell takes remainder
    const int c0 = x + cj * e;
    const int c1 = (cj < 2) ? (c0 + e) : (x + w);

    const int t = threadIdx.x;          // 0..63 -> float4 channel group
    const float4* __restrict__ f4 = (const float4*)feat;  // 64 float4 per pixel

    float4 m = make_float4(-FLT_MAX, -FLT_MAX, -FLT_MAX, -FLT_MAX);
    for (int r = r0; r < r1; ++r) {
        const float4* rowp = f4 + ((size_t)(b * HH + r) * WW) * (CC / 4) + t;
        #pragma unroll 4
        for (int c = c0; c < c1; ++c) {
            float4 v = __ldg(rowp + (size_t)c * (CC / 4));
            m.x = fmaxf(m.x, v.x);
            m.y = fmaxf(m.y, v.y);
            m.z = fmaxf(m.z, v.z);
            m.w = fmaxf(m.w, v.w);
        }
    }

    // pooled layout (B, N, 3, 3, C): offset = bid * C + 4t  (bid == box*9+cell)
    ((float4*)out)[(size_t)bid * (CC / 4) + t] = m;
}

// ---------------------------------------------------------------------------
// Launch: out = [pooled (B*N*3*3*C floats) | roi_clipped (B*N*4 as floats)]
// ---------------------------------------------------------------------------
extern "C" void kernel_launch(void* const* d_in, const int* in_sizes, int n_in,
                              void* d_out, int out_size) {
    const float* features = (const float*)d_in[0];  // (B,H,W,C) f32
    const float* roi      = (const float*)d_in[1];  // (B,R,4)  f32
    float* out = (float*)d_out;

    const int pooled_elems = BB * NREG * PS * PS * CC;  // 294912

    nms_clip_kernel<<<BB, RR>>>(roi, out + pooled_elems);
    pool_kernel<<<BB * NREG * 9, 64>>>(features, out);
}

// round 6
// speedup vs baseline: 1.0996x; 1.0996x over previous
#include <cuda_runtime.h>
#include <cuda_bf16.h>
#include <float.h>
#include <stdint.h>

// Problem constants
#define BB 4
#define RR 128
#define CC 256
#define HH 64
#define WW 64
#define NREG 32
#define PS 3            // pool size (3x3)
#define IOU_THR 0.4f

// Scratch for clipped integer boxes (B*N*4). Device global per allocation rules.
__device__ int g_boxes[BB * NREG * 4];

// ---------------------------------------------------------------------------
// Kernel 1: per-batch NMS + index selection + ROI clipping.
// One block per batch, 128 threads (one per box).
// ---------------------------------------------------------------------------
__device__ __forceinline__ void fix_axis(int& mn, int& mx, int ps, int fs) {
    int pad = ps - (mx - mn);
    if (pad > 0) {
        bool fmin = mn < (pad / 2);            // pad>0 -> trunc == floor
        bool fmx  = (fs - mx) < ((1 + pad) / 2);
        if (!fmin && !fmx) { mn = mn - pad / 2; mx = mx + (1 + pad) / 2; }
        if (fmin) { mn = 0; mx = ps; }
        if (fmx)  { mn = fs - ps; mx = fs; }   // fmx overrides fmin (ref order)
    }
}

__global__ void nms_clip_kernel(const float* __restrict__ roi,
                                float* __restrict__ out_roic) {
    __shared__ float sx1[RR], sy1[RR], sx2[RR], sy2[RR], sar[RR];
    __shared__ uint32_t sup[RR][4];
    __shared__ int sel[NREG];

    const int b = blockIdx.x;
    const int t = threadIdx.x;

    // Load box t of batch b
    const float* rp = roi + ((size_t)b * RR + t) * 4;
    float x = rp[0], y = rp[1], w = rp[2], h = rp[3];
    float x2 = x + w, y2 = y + h, ar = w * h;
    sx1[t] = x;  sy1[t] = y;  sx2[t] = x2;  sy2[t] = y2;  sar[t] = ar;
    __syncthreads();

    // Row t of the suppression matrix: bit j set iff j > t and IoU(t, j) > thr.
    uint32_t row0 = 0, row1 = 0, row2 = 0, row3 = 0;
    for (int j = t + 1; j < RR; ++j) {
        float iw = fminf(x2, sx2[j]) - fmaxf(x, sx1[j]);
        iw = fmaxf(iw, 0.0f);
        float ih = fminf(y2, sy2[j]) - fmaxf(y, sy1[j]);
        ih = fmaxf(ih, 0.0f);
        float inter = iw * ih;
        float uni   = ar + sar[j] - inter;
        float iou   = __fdiv_rn(inter, uni);   // IEEE rn (matches jnp fp32 div)
        if (iou > IOU_THR) {
            uint32_t bit = 1u << (j & 31);
            if      ((j >> 5) == 0) row0 |= bit;
            else if ((j >> 5) == 1) row1 |= bit;
            else if ((j >> 5) == 2) row2 |= bit;
            else                    row3 |= bit;
        }
    }
    sup[t][0] = row0; sup[t][1] = row1; sup[t][2] = row2; sup[t][3] = row3;
    __syncthreads();

    // Serial greedy walk on a 128-bit keep mask.
    // Branch-free: loads are unconditional (pipeline ahead), the dependency
    // chain is ALU-only (mask = 0 or ~0 from the keep bit).
    if (t == 0) {
        uint32_t k0 = ~0u, k1 = ~0u, k2 = ~0u, k3 = ~0u;
        #pragma unroll 4
        for (int p = 0; p < RR - 1; ++p) {
            uint32_t s0 = sup[p][0], s1 = sup[p][1];
            uint32_t s2 = sup[p][2], s3 = sup[p][3];
            uint32_t kw = (p < 32) ? k0 : (p < 64) ? k1 : (p < 96) ? k2 : k3;
            uint32_t msk = 0u - ((kw >> (p & 31)) & 1u);
            k0 &= ~(s0 & msk); k1 &= ~(s1 & msk);
            k2 &= ~(s2 & msk); k3 &= ~(s3 & msk);
        }
        // Collect first NREG kept indices ascending via ffs; pad with R-1.
        uint32_t kwords[4] = {k0, k1, k2, k3};
        int cnt = 0;
        #pragma unroll
        for (int wrd = 0; wrd < 4 && cnt < NREG; ++wrd) {
            uint32_t kw = kwords[wrd];
            while (kw && cnt < NREG) {
                int bit = __ffs(kw) - 1;
                sel[cnt++] = wrd * 32 + bit;
                kw &= kw - 1;
            }
        }
        for (; cnt < NREG; ++cnt) sel[cnt] = RR - 1;
    }
    __syncthreads();

    // Threads 0..31: clip the selected ROI, write int scratch + float output tail.
    if (t < NREG) {
        int p = sel[t];
        float bx = sx1[p], by = sy1[p], bx2 = sx2[p], by2 = sy2[p];
        int xmn = (int)fmaxf(0.0f, bx);
        int ymn = (int)fmaxf(0.0f, by);
        int xmx = (int)fminf((float)WW, bx2);
        int ymx = (int)fminf((float)HH, by2);
        fix_axis(xmn, xmx, PS, WW);
        fix_axis(ymn, ymx, PS, HH);

        int o = (b * NREG + t) * 4;
        g_boxes[o + 0] = xmn;
        g_boxes[o + 1] = ymn;
        g_boxes[o + 2] = xmx - xmn;
        g_boxes[o + 3] = ymx - ymn;
        out_roic[o + 0] = (float)xmn;
        out_roic[o + 1] = (float)ymn;
        out_roic[o + 2] = (float)(xmx - xmn);
        out_roic[o + 3] = (float)(ymx - ymn);
    }
}

// ---------------------------------------------------------------------------
// Kernel 2: max-pool each (box, cell). Grid = B*N*9 blocks, 256 threads.
// Threads form 4 pixel-groups x 64 channel-lanes (float4 per lane).
// Each group takes every 4th pixel of the flattened cell rectangle, so work
// is balanced even for skinny cells. A 4-way smem reduction merges groups.
// ---------------------------------------------------------------------------
__global__ void __launch_bounds__(256) pool_kernel(const float* __restrict__ feat,
                                                   float* __restrict__ out) {
    const int bid  = blockIdx.x;        // 0 .. B*N*9-1
    const int box  = bid / 9;           // 0 .. B*N-1
    const int cell = bid - box * 9;
    const int ci   = cell / 3;          // row cell
    const int cj   = cell - ci * 3;     // col cell
    const int b    = box >> 5;          // box / NREG

    const int x = g_boxes[box * 4 + 0];
    const int y = g_boxes[box * 4 + 1];
    const int w = g_boxes[box * 4 + 2];
    const int h = g_boxes[box * 4 + 3];

    const int d = h / PS;               // >= 1 (h >= 3 guaranteed by clip)
    const int e = w / PS;
    const int r0 = y + ci * d;
    const int r1 = (ci < 2) ? (r0 + d) : (y + h);   // last cell takes remainder
    const int c0 = x + cj * e;
    const int c1 = (cj < 2) ? (c0 + e) : (x + w);

    const int t  = threadIdx.x;
    const int g  = t >> 6;              // pixel group 0..3
    const int ch = t & 63;              // float4 channel lane

    const int ncol = c1 - c0;           // >= 1
    const int npix = (r1 - r0) * ncol;  // >= 1

    // base pointer for this batch image + channel lane
    const float4* __restrict__ f4 =
        (const float4*)feat + ((size_t)b * HH * WW) * (CC / 4) + ch;

    float4 m = make_float4(-FLT_MAX, -FLT_MAX, -FLT_MAX, -FLT_MAX);

    int r = r0 + g / ncol;
    int c = c0 + g % ncol;
    for (int i = g; i < npix; i += 4) {
        float4 v = __ldg(f4 + ((size_t)(r * WW + c)) * (CC / 4));
        m.x = fmaxf(m.x, v.x);
        m.y = fmaxf(m.y, v.y);
        m.z = fmaxf(m.z, v.z);
        m.w = fmaxf(m.w, v.w);
        c += 4;
        while (c >= c1) { c -= ncol; ++r; }
    }

    __shared__ float4 red[4][64];
    red[g][ch] = m;
    __syncthreads();

    if (t < 64) {
        float4 a0 = red[0][t], a1 = red[1][t], a2 = red[2][t], a3 = red[3][t];
        float4 o;
        o.x = fmaxf(fmaxf(a0.x, a1.x), fmaxf(a2.x, a3.x));
        o.y = fmaxf(fmaxf(a0.y, a1.y), fmaxf(a2.y, a3.y));
        o.z = fmaxf(fmaxf(a0.z, a1.z), fmaxf(a2.z, a3.z));
        o.w = fmaxf(fmaxf(a0.w, a1.w), fmaxf(a2.w, a3.w));
        // pooled layout (B, N, 3, 3, C): offset = bid * C + 4t
        ((float4*)out)[(size_t)bid * (CC / 4) + t] = o;
    }
}

// ---------------------------------------------------------------------------
// Launch: out = [pooled (B*N*3*3*C floats) | roi_clipped (B*N*4 as floats)]
// ---------------------------------------------------------------------------
extern "C" void kernel_launch(void* const* d_in, const int* in_sizes, int n_in,
                              void* d_out, int out_size) {
    const float* features = (const float*)d_in[0];  // (B,H,W,C) f32
    const float* roi      = (const float*)d_in[1];  // (B,R,4)  f32
    float* out = (float*)d_out;

    const int pooled_elems = BB * NREG * PS * PS * CC;  // 294912

    nms_clip_kernel<<<BB, RR>>>(roi, out + pooled_elems);
    pool_kernel<<<BB * NREG * 9, 256>>>(features, out);
}